// round 1
// baseline (speedup 1.0000x reference)
#include <cuda_runtime.h>
#include <cuda_bf16.h>
#include <cstdint>

#define NN    30000
#define EE    480000
#define KSUB  32
#define PP    16384
#define IND   1024
#define HD    512
#define ZD    128
#define BNC   8
#define DBC   16
#define DEC0D 144   // ZD + DBC

// ---------------- scratch (device globals; no allocation allowed) ----------
__device__ float g_u512[(size_t)NN * HD];
__device__ float g_a512[(size_t)NN * HD];
__device__ float g_h512[(size_t)NN * HD];
__device__ float g_u128[(size_t)NN * ZD];
__device__ float g_a128[(size_t)NN * ZD];
__device__ float g_z[(size_t)NN * ZD];
__device__ float g_zshf[(size_t)NN * ZD];
__device__ float g_znb[(size_t)NN * DEC0D];
__device__ float g_aznb[(size_t)NN * DEC0D];
__device__ float g_bilWT[ZD * ZD];

// ---------------- SGEMM: C[M,Nc] = A[M,K] @ B[K,Nc] (+bias) ---------------
// BM=128, BN=128, BK=8, 256 threads, 8x8 per-thread tile.
// Requires: K % 8 == 0, Nc % 128 == 0, rows 16B-aligned (all true here).
__global__ __launch_bounds__(256) void sgemm_k(
    int M, int Nc, int Kd,
    const float* __restrict__ A, const float* __restrict__ B,
    const float* __restrict__ bias, float* __restrict__ C)
{
    __shared__ float As[8][128];
    __shared__ float Bs[8][128];

    const int tid  = threadIdx.x;
    const int brow = blockIdx.x * 128;
    const int bcol = blockIdx.y * 128;

    const int trow = (tid >> 4) * 8;   // 16 thread-rows
    const int tcol = (tid & 15) * 8;   // 16 thread-cols

    const int arow = tid >> 1;         // 128 rows, 2 threads/row
    const int acol = (tid & 1) * 4;
    const int brw  = tid >> 5;         // 8 rows of B tile
    const int bcl  = (tid & 31) * 4;

    float acc[8][8];
#pragma unroll
    for (int i = 0; i < 8; i++)
#pragma unroll
        for (int j = 0; j < 8; j++) acc[i][j] = 0.f;

    const bool arow_ok = (brow + arow) < M;
    const float* Aptr = A + (size_t)(brow + arow) * Kd + acol;
    const float* Bptr = B + (size_t)brw * Nc + bcol + bcl;

    for (int k0 = 0; k0 < Kd; k0 += 8) {
        float4 av = make_float4(0.f, 0.f, 0.f, 0.f);
        if (arow_ok) av = *(const float4*)(Aptr + k0);
        As[acol + 0][arow] = av.x;
        As[acol + 1][arow] = av.y;
        As[acol + 2][arow] = av.z;
        As[acol + 3][arow] = av.w;

        float4 bv = *(const float4*)(Bptr + (size_t)k0 * Nc);
        *(float4*)&Bs[brw][bcl] = bv;
        __syncthreads();

#pragma unroll
        for (int kk = 0; kk < 8; kk++) {
            float ar[8], br[8];
            *(float4*)&ar[0] = *(float4*)&As[kk][trow];
            *(float4*)&ar[4] = *(float4*)&As[kk][trow + 4];
            *(float4*)&br[0] = *(float4*)&Bs[kk][tcol];
            *(float4*)&br[4] = *(float4*)&Bs[kk][tcol + 4];
#pragma unroll
            for (int i = 0; i < 8; i++)
#pragma unroll
                for (int j = 0; j < 8; j++)
                    acc[i][j] = fmaf(ar[i], br[j], acc[i][j]);
        }
        __syncthreads();
    }

#pragma unroll
    for (int i = 0; i < 8; i++) {
        int r = brow + trow + i;
        if (r < M) {
#pragma unroll
            for (int j = 0; j < 8; j += 4) {
                float4 v;
                v.x = acc[i][j + 0];
                v.y = acc[i][j + 1];
                v.z = acc[i][j + 2];
                v.w = acc[i][j + 3];
                if (bias) {
                    v.x += bias[bcol + tcol + j + 0];
                    v.y += bias[bcol + tcol + j + 1];
                    v.z += bias[bcol + tcol + j + 2];
                    v.w += bias[bcol + tcol + j + 3];
                }
                *(float4*)(C + (size_t)r * Nc + bcol + tcol + j) = v;
            }
        }
    }
}

// ---------------- float4 copy -------------------------------------------
__global__ void copy4_k(float4* __restrict__ dst, const float4* __restrict__ src, int n4)
{
    int i = blockIdx.x * blockDim.x + threadIdx.x;
    if (i < n4) dst[i] = src[i];
}

// ---------------- edge aggregation: agg[dst] += u[src] (warp per edge) ----
__global__ void agg_k(const float* __restrict__ u, float* __restrict__ agg,
                      const int* __restrict__ src, const int* __restrict__ dst, int D)
{
    int w = (blockIdx.x * blockDim.x + threadIdx.x) >> 5;
    if (w >= EE) return;
    int lane = threadIdx.x & 31;
    int s = __ldg(src + w);
    int d = __ldg(dst + w);
    const float4* up = (const float4*)(u + (size_t)s * D);
    float* ap = agg + (size_t)d * D;
    int D4 = D >> 2;
    for (int c = lane; c < D4; c += 32) {
        float4 v = up[c];
        asm volatile("red.global.add.v4.f32 [%0], {%1,%2,%3,%4};"
                     :: "l"(ap + 4 * c), "f"(v.x), "f"(v.y), "f"(v.z), "f"(v.w)
                     : "memory");
    }
}

// ---------------- LayerNorm(+bias)+ReLU, block per row --------------------
__global__ void ln_relu_k(const float* __restrict__ v, const float* __restrict__ b,
                          float* __restrict__ out, int D)
{
    int row = blockIdx.x;
    int t = threadIdx.x;   // 128 threads
    const float* vr = v + (size_t)row * D;
    float* orow = out + (size_t)row * D;
    int per = D >> 7;      // 1 (D=128) or 4 (D=512)
    float vals[4];
    float s = 0.f, ss = 0.f;
    for (int c = 0; c < per; c++) {
        float x = vr[c * 128 + t] + b[c * 128 + t];
        vals[c] = x;
        s += x; ss += x * x;
    }
#pragma unroll
    for (int o = 16; o > 0; o >>= 1) {
        s  += __shfl_xor_sync(0xffffffffu, s, o);
        ss += __shfl_xor_sync(0xffffffffu, ss, o);
    }
    __shared__ float sh[8];
    int wid = t >> 5;
    if ((t & 31) == 0) { sh[wid] = s; sh[4 + wid] = ss; }
    __syncthreads();
    float st  = sh[0] + sh[1] + sh[2] + sh[3];
    float sst = sh[4] + sh[5] + sh[6] + sh[7];
    float mean = st / D;
    float var  = sst / D - mean * mean;
    float inv  = rsqrtf(var + 1e-5f);
    for (int c = 0; c < per; c++)
        orow[c * 128 + t] = fmaxf((vals[c] - mean) * inv, 0.f);
}

// ---------------- subgraph mean pool (warp per node, K=32, Z=128) ---------
__global__ void pool_k(const float* __restrict__ z, const int* __restrict__ idx,
                       float* __restrict__ out)
{
    int w = (blockIdx.x * blockDim.x + threadIdx.x) >> 5;
    if (w >= NN) return;
    int lane = threadIdx.x & 31;
    int mi = __ldg(idx + (size_t)w * KSUB + lane);
    float4 acc = make_float4(0.f, 0.f, 0.f, 0.f);
#pragma unroll
    for (int k = 0; k < KSUB; k++) {
        int j = __shfl_sync(0xffffffffu, mi, k);
        float4 v = ((const float4*)(z + (size_t)j * ZD))[lane];
        acc.x += v.x; acc.y += v.y; acc.z += v.z; acc.w += v.w;
    }
    const float s = 1.f / KSUB;
    float4 o = make_float4(acc.x * s, acc.y * s, acc.z * s, acc.w * s);
    ((float4*)(out + (size_t)w * ZD))[lane] = o;
}

// ---------------- batch encoder MLP: writes znb[:,128:144] ---------------
__global__ void bemb_k(const float* __restrict__ bl,
                       const float* __restrict__ W0, const float* __restrict__ b0,
                       const float* __restrict__ W1, const float* __restrict__ b1,
                       float* __restrict__ znb)
{
    int i = blockIdx.x * blockDim.x + threadIdx.x;
    if (i >= NN) return;
    float in[BNC];
#pragma unroll
    for (int k = 0; k < BNC; k++) in[k] = bl[(size_t)i * BNC + k];
    float h[12];
#pragma unroll
    for (int j = 0; j < 12; j++) {
        float a = b0[j];
#pragma unroll
        for (int k = 0; k < BNC; k++) a = fmaf(in[k], W0[k * 12 + j], a);
        h[j] = fmaxf(a, 0.f);
    }
#pragma unroll
    for (int j = 0; j < DBC; j++) {
        float a = b1[j];
#pragma unroll
        for (int k = 0; k < 12; k++) a = fmaf(h[k], W1[k * DBC + j], a);
        znb[(size_t)i * DEC0D + ZD + j] = a;
    }
}

// ---------------- copy z_node into znb[:,0:128] ---------------------------
__global__ void zcat_k(const float* __restrict__ z, float* __restrict__ znb)
{
    int i = blockIdx.x * blockDim.x + threadIdx.x;   // over NN*32 float4s
    if (i >= NN * 32) return;
    int node = i >> 5, c = i & 31;
    ((float4*)(znb + (size_t)node * DEC0D))[c] =
        ((const float4*)(z + (size_t)node * ZD))[c];
}

// ---------------- batch discriminator head (block of 64 per node) ---------
__global__ void bd_head_k(const float* __restrict__ zsub,
                          const float* __restrict__ W0, const float* __restrict__ b0,
                          const float* __restrict__ W1, const float* __restrict__ b1,
                          float* __restrict__ out)
{
    int i = blockIdx.x;
    int j = threadIdx.x;  // 64
    __shared__ float zs[128];
    __shared__ float hs[64];
    zs[j]      = zsub[(size_t)i * ZD + j];
    zs[j + 64] = zsub[(size_t)i * ZD + 64 + j];
    __syncthreads();
    float a = b0[j];
#pragma unroll 8
    for (int k = 0; k < 128; k++) a = fmaf(zs[k], W0[k * 64 + j], a);
    hs[j] = fmaxf(a, 0.f);
    __syncthreads();
    if (j < BNC) {
        float o = b1[j];
#pragma unroll 8
        for (int k = 0; k < 64; k++) o = fmaf(hs[k], W1[k * BNC + j], o);
        out[(size_t)i * BNC + j] = o;
    }
}

// ---------------- transpose 128x128 (bil_W -> bil_W^T) --------------------
__global__ void tr128_k(const float* __restrict__ W, float* __restrict__ WT)
{
    int i = blockIdx.x * blockDim.x + threadIdx.x;
    if (i >= ZD * ZD) return;
    int r = i >> 7, c = i & 127;
    WT[c * ZD + r] = W[i];
}

// ---------------- bilinear pair dots (warp per pair) ----------------------
__global__ void pair_k(const float* __restrict__ zsub, const float* __restrict__ Mm,
                       const int* __restrict__ pos, const int* __restrict__ neg,
                       float* __restrict__ lp, float* __restrict__ lng)
{
    int w = (blockIdx.x * blockDim.x + threadIdx.x) >> 5;
    if (w >= 2 * PP) return;
    int lane = threadIdx.x & 31;
    bool isneg = (w >= PP);
    int p = isneg ? w - PP : w;
    int ia = __ldg(pos + p);
    int ib = isneg ? __ldg(neg + p) : ia;
    float4 a = ((const float4*)(zsub + (size_t)ia * ZD))[lane];
    float4 b = ((const float4*)(Mm + (size_t)ib * ZD))[lane];
    float s = a.x * b.x + a.y * b.y + a.z * b.z + a.w * b.w;
#pragma unroll
    for (int o = 16; o > 0; o >>= 1) s += __shfl_xor_sync(0xffffffffu, s, o);
    if (lane == 0) (isneg ? lng : lp)[p] = s;
}

// =========================================================================
extern "C" void kernel_launch(void* const* d_in, const int* in_sizes, int n_in,
                              void* d_out, int out_size)
{
    const float* x     = (const float*)d_in[0];
    const float* x_shf = (const float*)d_in[1];
    const float* bl    = (const float*)d_in[2];
    const float* encW0 = (const float*)d_in[3];
    const float* encb0 = (const float*)d_in[4];
    const float* encW1 = (const float*)d_in[5];
    const float* encb1 = (const float*)d_in[6];
    const float* decW0 = (const float*)d_in[7];
    const float* decb0 = (const float*)d_in[8];
    const float* decW1 = (const float*)d_in[9];
    const float* decb1 = (const float*)d_in[10];
    const float* beW0  = (const float*)d_in[11];
    const float* beb0  = (const float*)d_in[12];
    const float* beW1  = (const float*)d_in[13];
    const float* beb1  = (const float*)d_in[14];
    const float* bdW0  = (const float*)d_in[15];
    const float* bdb0  = (const float*)d_in[16];
    const float* bdW1  = (const float*)d_in[17];
    const float* bdb1  = (const float*)d_in[18];
    const float* bilW  = (const float*)d_in[19];
    const int*   eidx  = (const int*)d_in[20];
    const int*   subix = (const int*)d_in[21];
    const int*   pos   = (const int*)d_in[22];
    const int*   neg   = (const int*)d_in[23];
    const int* src = eidx;
    const int* dst = eidx + EE;

    float* out     = (float*)d_out;
    float* o_zsub  = out;
    float* o_zshf  = o_zsub  + (size_t)NN * ZD;
    float* o_recon = o_zshf  + (size_t)NN * ZD;
    float* o_lp    = o_recon + (size_t)NN * IND;
    float* o_ln    = o_lp + PP;
    float* o_lb    = o_ln + PP;

    float *u512, *a512, *h512, *u128, *a128, *z, *zshf, *znb, *aznb, *bilWT;
    cudaGetSymbolAddress((void**)&u512,  g_u512);
    cudaGetSymbolAddress((void**)&a512,  g_a512);
    cudaGetSymbolAddress((void**)&h512,  g_h512);
    cudaGetSymbolAddress((void**)&u128,  g_u128);
    cudaGetSymbolAddress((void**)&a128,  g_a128);
    cudaGetSymbolAddress((void**)&z,     g_z);
    cudaGetSymbolAddress((void**)&zshf,  g_zshf);
    cudaGetSymbolAddress((void**)&znb,   g_znb);
    cudaGetSymbolAddress((void**)&aznb,  g_aznb);
    cudaGetSymbolAddress((void**)&bilWT, g_bilWT);

    const int GM = (NN + 127) / 128;                 // 235
    const int AGG_BLOCKS = (EE * 32 + 255) / 256;    // warp per edge

    // ---- encoder pass (shared for x and x_shf) ----
    auto encode = [&](const float* xin, float* zout) {
        sgemm_k<<<dim3(GM, HD / 128), 256>>>(NN, HD, IND, xin, encW0, nullptr, u512);
        {
            int n4 = NN * HD / 4;
            copy4_k<<<(n4 + 255) / 256, 256>>>((float4*)a512, (const float4*)u512, n4);
        }
        agg_k<<<AGG_BLOCKS, 256>>>(u512, a512, src, dst, HD);
        ln_relu_k<<<NN, 128>>>(a512, encb0, h512, HD);

        sgemm_k<<<dim3(GM, ZD / 128), 256>>>(NN, ZD, HD, h512, encW1, nullptr, u128);
        {
            int n4 = NN * ZD / 4;
            copy4_k<<<(n4 + 255) / 256, 256>>>((float4*)a128, (const float4*)u128, n4);
        }
        agg_k<<<AGG_BLOCKS, 256>>>(u128, a128, src, dst, ZD);
        ln_relu_k<<<NN, 128>>>(a128, encb1, zout, ZD);
    };

    encode(x, z);
    pool_k<<<(NN * 32 + 255) / 256, 256>>>(z, subix, o_zsub);

    encode(x_shf, zshf);
    pool_k<<<(NN * 32 + 255) / 256, 256>>>(zshf, subix, o_zshf);

    // ---- decoder ----
    zcat_k<<<(NN * 32 + 255) / 256, 256>>>(z, znb);
    bemb_k<<<(NN + 255) / 256, 256>>>(bl, beW0, beb0, beW1, beb1, znb);
    {
        int n4 = NN * DEC0D / 4;
        copy4_k<<<(n4 + 255) / 256, 256>>>((float4*)aznb, (const float4*)znb, n4);
    }
    agg_k<<<AGG_BLOCKS, 256>>>(znb, aznb, src, dst, DEC0D);
    sgemm_k<<<dim3(GM, HD / 128), 256>>>(NN, HD, DEC0D, aznb, decW0, nullptr, u512);
    ln_relu_k<<<NN, 128>>>(u512, decb0, h512, HD);
    {
        int n4 = NN * HD / 4;
        copy4_k<<<(n4 + 255) / 256, 256>>>((float4*)a512, (const float4*)h512, n4);
    }
    agg_k<<<AGG_BLOCKS, 256>>>(h512, a512, src, dst, HD);
    sgemm_k<<<dim3(GM, IND / 128), 256>>>(NN, IND, HD, a512, decW1, decb1, o_recon);

    // ---- heads ----
    bd_head_k<<<NN, 64>>>(o_zsub, bdW0, bdb0, bdW1, bdb1, o_lb);
    tr128_k<<<(ZD * ZD + 255) / 256, 256>>>(bilW, bilWT);
    // M = z_sub_shf @ bil_W^T   (so logits = dot(z_sub[pos], M[ind]))
    sgemm_k<<<dim3(GM, ZD / 128), 256>>>(NN, ZD, ZD, o_zshf, bilWT, nullptr, u128);
    pair_k<<<(2 * PP * 32 + 255) / 256, 256>>>(o_zsub, u128, pos, neg, o_lp, o_ln);
}

// round 4
// speedup vs baseline: 2.0623x; 2.0623x over previous
#include <cuda_runtime.h>
#include <cuda_bf16.h>
#include <cstdint>

#define NN    30000
#define EE    480000
#define KSUB  32
#define PP    16384
#define IND   1024
#define HD    512
#define ZD    128
#define BNC   8
#define DBC   16
#define DEC0D 144   // ZD + DBC

// ---------------- scratch (device globals; no allocation allowed) ----------
__device__ float g_u512[(size_t)NN * HD];
__device__ float g_a512[(size_t)NN * HD];
__device__ float g_h512[(size_t)NN * HD];
__device__ float g_u128[(size_t)NN * ZD];
__device__ float g_a128[(size_t)NN * ZD];
__device__ float g_z[(size_t)NN * ZD];
__device__ float g_zshf[(size_t)NN * ZD];
__device__ float g_znb[(size_t)NN * DEC0D];
__device__ float g_aznb[(size_t)NN * DEC0D];
// transposed weights (B^T, [N,K] K-major)
__device__ float g_encW0T[(size_t)HD * IND];
__device__ float g_encW1T[(size_t)ZD * HD];
__device__ float g_decW0T[(size_t)HD * DEC0D];
__device__ float g_decW1T[(size_t)IND * HD];

// ======================= mma.sync tf32 helpers ===========================
__device__ __forceinline__ uint32_t su32(const void* p) {
    return (uint32_t)__cvta_generic_to_shared(p);
}
__device__ __forceinline__ uint32_t f2tf32(float x) {
    uint32_t u;
    asm("cvt.rna.tf32.f32 %0, %1;" : "=r"(u) : "f"(x));
    return u;
}
__device__ __forceinline__ void ldsm4(uint32_t* r, uint32_t addr) {
    asm volatile("ldmatrix.sync.aligned.m8n8.x4.shared.b16 {%0,%1,%2,%3}, [%4];"
                 : "=r"(r[0]), "=r"(r[1]), "=r"(r[2]), "=r"(r[3]) : "r"(addr));
}
__device__ __forceinline__ void mma_tf32(float* c, const uint32_t* a, const uint32_t* b) {
    asm volatile(
        "mma.sync.aligned.m16n8k8.row.col.f32.tf32.tf32.f32 "
        "{%0,%1,%2,%3}, {%4,%5,%6,%7}, {%8,%9}, {%0,%1,%2,%3};"
        : "+f"(c[0]), "+f"(c[1]), "+f"(c[2]), "+f"(c[3])
        : "r"(a[0]), "r"(a[1]), "r"(a[2]), "r"(a[3]), "r"(b[0]), "r"(b[1]));
}

// ---------------- tensor-core tf32 GEMM (mma.sync) ------------------------
// C[M,Nc] = A[M,Kd] @ B[Kd,Nc], B given transposed as BT[Nc,Kd].
// Block 128x128xBK16, 8 warps (2x4), warp tile 64x32. Kd%16==0, Nc%128==0.
#define RS 20   // SMEM row stride (floats); 80B -> conflict-free ldmatrix
__global__ __launch_bounds__(256) void mmagemm_k(
    int M, int Nc, int Kd,
    const float* __restrict__ A, const float* __restrict__ BT,
    const float* __restrict__ bias, float* __restrict__ C)
{
    __shared__ __align__(16) float As[128 * RS];
    __shared__ __align__(16) float Bs[128 * RS];

    const int tid  = threadIdx.x;
    const int lane = tid & 31;
    const int wid  = tid >> 5;
    const int wm   = wid >> 2;        // 0..1
    const int wn   = wid & 3;         // 0..3
    const int brow = blockIdx.x * 128;
    const int bcol = blockIdx.y * 128;

    const uint32_t as_b = su32(As);
    const uint32_t bs_b = su32(Bs);

    float c[4][4][4];
#pragma unroll
    for (int i = 0; i < 4; i++)
#pragma unroll
        for (int j = 0; j < 4; j++)
#pragma unroll
            for (int k = 0; k < 4; k++) c[i][j][k] = 0.f;

    // global <-> smem staging indices: 2 rows per thread per tile
    const int lr = tid >> 2;          // 0..63
    const int lc = (tid & 3) * 4;     // k offset (floats)

    float4 ra[2], rb[2];
    auto ldg = [&](int k0) {
#pragma unroll
        for (int p = 0; p < 2; p++) {
            const int r = p * 64 + lr;
            const int gr = brow + r;
            float4 v = make_float4(0.f, 0.f, 0.f, 0.f);
            if (gr < M) v = *(const float4*)(A + (size_t)gr * Kd + k0 + lc);
            ra[p] = v;
            rb[p] = *(const float4*)(BT + (size_t)(bcol + r) * Kd + k0 + lc);
        }
    };
    auto sts = [&]() {
#pragma unroll
        for (int p = 0; p < 2; p++) {
            const int r = p * 64 + lr;
            uint4 va, vb;
            va.x = f2tf32(ra[p].x); va.y = f2tf32(ra[p].y);
            va.z = f2tf32(ra[p].z); va.w = f2tf32(ra[p].w);
            vb.x = f2tf32(rb[p].x); vb.y = f2tf32(rb[p].y);
            vb.z = f2tf32(rb[p].z); vb.w = f2tf32(rb[p].w);
            *(uint4*)(As + r * RS + lc) = va;
            *(uint4*)(Bs + r * RS + lc) = vb;
        }
    };

    const int nch = Kd >> 4;
    const int l8 = lane & 7;
    const int lm = lane >> 3;         // matrix id 0..3

    ldg(0);

    for (int ci = 0; ci < nch; ci++) {
        __syncthreads();
        sts();
        __syncthreads();
        if (ci + 1 < nch) ldg((ci + 1) * 16);

#pragma unroll
        for (int ks = 0; ks < 2; ks++) {
            uint32_t af[4][4], bf[2][4];
#pragma unroll
            for (int mt = 0; mt < 4; mt++) {
                // matrices: row += (lm&1)*8, k += (lm>>1)*4
                const int r = wm * 64 + mt * 16 + l8 + (lm & 1) * 8;
                const int k = ks * 8 + (lm >> 1) * 4;
                ldsm4(af[mt], as_b + (uint32_t)(r * RS + k) * 4u);
            }
#pragma unroll
            for (int np = 0; np < 2; np++) {
                // matrices: n += (lm>>1)*8, k += (lm&1)*4
                const int n = wn * 32 + np * 16 + l8 + (lm >> 1) * 8;
                const int k = ks * 8 + (lm & 1) * 4;
                ldsm4(bf[np], bs_b + (uint32_t)(n * RS + k) * 4u);
            }
#pragma unroll
            for (int mt = 0; mt < 4; mt++) {
#pragma unroll
                for (int np = 0; np < 2; np++) {
                    mma_tf32(c[mt][np * 2 + 0], af[mt], &bf[np][0]);
                    mma_tf32(c[mt][np * 2 + 1], af[mt], &bf[np][2]);
                }
            }
        }
    }

    // epilogue
    const int row0 = brow + wm * 64 + (lane >> 2);
    const int col0 = bcol + wn * 32 + (lane & 3) * 2;
#pragma unroll
    for (int mt = 0; mt < 4; mt++) {
#pragma unroll
        for (int nt = 0; nt < 4; nt++) {
            const int cc = col0 + nt * 8;
            float bx = 0.f, by = 0.f;
            if (bias) { bx = bias[cc]; by = bias[cc + 1]; }
            const int r0 = row0 + mt * 16;
            if (r0 < M) {
                float2 v = make_float2(c[mt][nt][0] + bx, c[mt][nt][1] + by);
                *(float2*)(C + (size_t)r0 * Nc + cc) = v;
            }
            if (r0 + 8 < M) {
                float2 v = make_float2(c[mt][nt][2] + bx, c[mt][nt][3] + by);
                *(float2*)(C + (size_t)(r0 + 8) * Nc + cc) = v;
            }
        }
    }
}

// ---------------- weight transpose: out[C][R] = in[R][C] ------------------
__global__ void transpose_k(const float* __restrict__ in, float* __restrict__ out,
                            int R, int C)
{
    __shared__ float t[32][33];
    int bx = blockIdx.x * 32, by = blockIdx.y * 32;
    int x = bx + threadIdx.x;
#pragma unroll
    for (int j = 0; j < 32; j += 8) {
        int y = by + threadIdx.y + j;
        if (x < C && y < R) t[threadIdx.y + j][threadIdx.x] = in[(size_t)y * C + x];
    }
    __syncthreads();
    int ox = by + threadIdx.x;
#pragma unroll
    for (int j = 0; j < 32; j += 8) {
        int oy = bx + threadIdx.y + j;
        if (ox < R && oy < C) out[(size_t)oy * R + ox] = t[threadIdx.x][threadIdx.y + j];
    }
}

// ---------------- float4 copy -------------------------------------------
__global__ void copy4_k(float4* __restrict__ dst, const float4* __restrict__ src, int n4)
{
    int i = blockIdx.x * blockDim.x + threadIdx.x;
    if (i < n4) dst[i] = src[i];
}

// ---------------- edge aggregation: agg[dst] += u[src] (warp per edge) ----
__global__ void agg_k(const float* __restrict__ u, float* __restrict__ agg,
                      const int* __restrict__ src, const int* __restrict__ dst, int D)
{
    int w = (blockIdx.x * blockDim.x + threadIdx.x) >> 5;
    if (w >= EE) return;
    int lane = threadIdx.x & 31;
    int s = __ldg(src + w);
    int d = __ldg(dst + w);
    const float4* up = (const float4*)(u + (size_t)s * D);
    float* ap = agg + (size_t)d * D;
    int D4 = D >> 2;
    for (int c = lane; c < D4; c += 32) {
        float4 v = up[c];
        asm volatile("red.global.add.v4.f32 [%0], {%1,%2,%3,%4};"
                     :: "l"(ap + 4 * c), "f"(v.x), "f"(v.y), "f"(v.z), "f"(v.w)
                     : "memory");
    }
}

// ---------------- LayerNorm(+bias)+ReLU, block per row --------------------
__global__ void ln_relu_k(const float* __restrict__ v, const float* __restrict__ b,
                          float* __restrict__ out, int D)
{
    int row = blockIdx.x;
    int t = threadIdx.x;   // 128 threads
    const float* vr = v + (size_t)row * D;
    float* orow = out + (size_t)row * D;
    int per = D >> 7;
    float vals[4];
    float s = 0.f, ss = 0.f;
    for (int c = 0; c < per; c++) {
        float x = vr[c * 128 + t] + b[c * 128 + t];
        vals[c] = x;
        s += x; ss += x * x;
    }
#pragma unroll
    for (int o = 16; o > 0; o >>= 1) {
        s  += __shfl_xor_sync(0xffffffffu, s, o);
        ss += __shfl_xor_sync(0xffffffffu, ss, o);
    }
    __shared__ float sh[8];
    int wid = t >> 5;
    if ((t & 31) == 0) { sh[wid] = s; sh[4 + wid] = ss; }
    __syncthreads();
    float st  = sh[0] + sh[1] + sh[2] + sh[3];
    float sst = sh[4] + sh[5] + sh[6] + sh[7];
    float mean = st / D;
    float var  = sst / D - mean * mean;
    float inv  = rsqrtf(var + 1e-5f);
    for (int c = 0; c < per; c++)
        orow[c * 128 + t] = fmaxf((vals[c] - mean) * inv, 0.f);
}

// ---------------- subgraph mean pool (warp per node, K=32, Z=128) ---------
__global__ void pool_k(const float* __restrict__ z, const int* __restrict__ idx,
                       float* __restrict__ out)
{
    int w = (blockIdx.x * blockDim.x + threadIdx.x) >> 5;
    if (w >= NN) return;
    int lane = threadIdx.x & 31;
    int mi = __ldg(idx + (size_t)w * KSUB + lane);
    float4 acc = make_float4(0.f, 0.f, 0.f, 0.f);
#pragma unroll
    for (int k = 0; k < KSUB; k++) {
        int j = __shfl_sync(0xffffffffu, mi, k);
        float4 v = ((const float4*)(z + (size_t)j * ZD))[lane];
        acc.x += v.x; acc.y += v.y; acc.z += v.z; acc.w += v.w;
    }
    const float s = 1.f / KSUB;
    float4 o = make_float4(acc.x * s, acc.y * s, acc.z * s, acc.w * s);
    ((float4*)(out + (size_t)w * ZD))[lane] = o;
}

// ---------------- batch encoder MLP: writes znb[:,128:144] ---------------
__global__ void bemb_k(const float* __restrict__ bl,
                       const float* __restrict__ W0, const float* __restrict__ b0,
                       const float* __restrict__ W1, const float* __restrict__ b1,
                       float* __restrict__ znb)
{
    int i = blockIdx.x * blockDim.x + threadIdx.x;
    if (i >= NN) return;
    float in[BNC];
#pragma unroll
    for (int k = 0; k < BNC; k++) in[k] = bl[(size_t)i * BNC + k];
    float h[12];
#pragma unroll
    for (int j = 0; j < 12; j++) {
        float a = b0[j];
#pragma unroll
        for (int k = 0; k < BNC; k++) a = fmaf(in[k], W0[k * 12 + j], a);
        h[j] = fmaxf(a, 0.f);
    }
#pragma unroll
    for (int j = 0; j < DBC; j++) {
        float a = b1[j];
#pragma unroll
        for (int k = 0; k < 12; k++) a = fmaf(h[k], W1[k * DBC + j], a);
        znb[(size_t)i * DEC0D + ZD + j] = a;
    }
}

// ---------------- copy z_node into znb[:,0:128] ---------------------------
__global__ void zcat_k(const float* __restrict__ z, float* __restrict__ znb)
{
    int i = blockIdx.x * blockDim.x + threadIdx.x;
    if (i >= NN * 32) return;
    int node = i >> 5, c = i & 31;
    ((float4*)(znb + (size_t)node * DEC0D))[c] =
        ((const float4*)(z + (size_t)node * ZD))[c];
}

// ---------------- batch discriminator head (block of 64 per node) ---------
__global__ void bd_head_k(const float* __restrict__ zsub,
                          const float* __restrict__ W0, const float* __restrict__ b0,
                          const float* __restrict__ W1, const float* __restrict__ b1,
                          float* __restrict__ out)
{
    int i = blockIdx.x;
    int j = threadIdx.x;  // 64
    __shared__ float zs[128];
    __shared__ float hs[64];
    zs[j]      = zsub[(size_t)i * ZD + j];
    zs[j + 64] = zsub[(size_t)i * ZD + 64 + j];
    __syncthreads();
    float a = b0[j];
#pragma unroll 8
    for (int k = 0; k < 128; k++) a = fmaf(zs[k], W0[k * 64 + j], a);
    hs[j] = fmaxf(a, 0.f);
    __syncthreads();
    if (j < BNC) {
        float o = b1[j];
#pragma unroll 8
        for (int k = 0; k < 64; k++) o = fmaf(hs[k], W1[k * BNC + j], o);
        out[(size_t)i * BNC + j] = o;
    }
}

// ---------------- bilinear pair dots (warp per pair) ----------------------
__global__ void pair_k(const float* __restrict__ zsub, const float* __restrict__ Mm,
                       const int* __restrict__ pos, const int* __restrict__ neg,
                       float* __restrict__ lp, float* __restrict__ lng)
{
    int w = (blockIdx.x * blockDim.x + threadIdx.x) >> 5;
    if (w >= 2 * PP) return;
    int lane = threadIdx.x & 31;
    bool isneg = (w >= PP);
    int p = isneg ? w - PP : w;
    int ia = __ldg(pos + p);
    int ib = isneg ? __ldg(neg + p) : ia;
    float4 a = ((const float4*)(zsub + (size_t)ia * ZD))[lane];
    float4 b = ((const float4*)(Mm + (size_t)ib * ZD))[lane];
    float s = a.x * b.x + a.y * b.y + a.z * b.z + a.w * b.w;
#pragma unroll
    for (int o = 16; o > 0; o >>= 1) s += __shfl_xor_sync(0xffffffffu, s, o);
    if (lane == 0) (isneg ? lng : lp)[p] = s;
}

// =========================================================================
extern "C" void kernel_launch(void* const* d_in, const int* in_sizes, int n_in,
                              void* d_out, int out_size)
{
    const float* x     = (const float*)d_in[0];
    const float* x_shf = (const float*)d_in[1];
    const float* bl    = (const float*)d_in[2];
    const float* encW0 = (const float*)d_in[3];
    const float* encb0 = (const float*)d_in[4];
    const float* encW1 = (const float*)d_in[5];
    const float* encb1 = (const float*)d_in[6];
    const float* decW0 = (const float*)d_in[7];
    const float* decb0 = (const float*)d_in[8];
    const float* decW1 = (const float*)d_in[9];
    const float* decb1 = (const float*)d_in[10];
    const float* beW0  = (const float*)d_in[11];
    const float* beb0  = (const float*)d_in[12];
    const float* beW1  = (const float*)d_in[13];
    const float* beb1  = (const float*)d_in[14];
    const float* bdW0  = (const float*)d_in[15];
    const float* bdb0  = (const float*)d_in[16];
    const float* bdW1  = (const float*)d_in[17];
    const float* bdb1  = (const float*)d_in[18];
    const float* bilW  = (const float*)d_in[19];
    const int*   eidx  = (const int*)d_in[20];
    const int*   subix = (const int*)d_in[21];
    const int*   pos   = (const int*)d_in[22];
    const int*   neg   = (const int*)d_in[23];
    const int* src = eidx;
    const int* dst = eidx + EE;

    float* out     = (float*)d_out;
    float* o_zsub  = out;
    float* o_zshf  = o_zsub  + (size_t)NN * ZD;
    float* o_recon = o_zshf  + (size_t)NN * ZD;
    float* o_lp    = o_recon + (size_t)NN * IND;
    float* o_ln    = o_lp + PP;
    float* o_lb    = o_ln + PP;

    float *u512, *a512, *h512, *u128, *a128, *z, *zshf, *znb, *aznb;
    float *encW0T, *encW1T, *decW0T, *decW1T;
    cudaGetSymbolAddress((void**)&u512,  g_u512);
    cudaGetSymbolAddress((void**)&a512,  g_a512);
    cudaGetSymbolAddress((void**)&h512,  g_h512);
    cudaGetSymbolAddress((void**)&u128,  g_u128);
    cudaGetSymbolAddress((void**)&a128,  g_a128);
    cudaGetSymbolAddress((void**)&z,     g_z);
    cudaGetSymbolAddress((void**)&zshf,  g_zshf);
    cudaGetSymbolAddress((void**)&znb,   g_znb);
    cudaGetSymbolAddress((void**)&aznb,  g_aznb);
    cudaGetSymbolAddress((void**)&encW0T, g_encW0T);
    cudaGetSymbolAddress((void**)&encW1T, g_encW1T);
    cudaGetSymbolAddress((void**)&decW0T, g_decW0T);
    cudaGetSymbolAddress((void**)&decW1T, g_decW1T);

    const int GM = (NN + 127) / 128;                 // 235
    const int AGG_BLOCKS = (EE * 32 + 255) / 256;    // warp per edge
    dim3 tb(32, 8);

    // ---- weight transposes (BT = [N, K]) ----
    transpose_k<<<dim3((HD + 31) / 32, (IND + 31) / 32), tb>>>(encW0, encW0T, IND, HD);
    transpose_k<<<dim3((ZD + 31) / 32, (HD + 31) / 32), tb>>>(encW1, encW1T, HD, ZD);
    transpose_k<<<dim3((HD + 31) / 32, (DEC0D + 31) / 32), tb>>>(decW0, decW0T, DEC0D, HD);
    transpose_k<<<dim3((IND + 31) / 32, (HD + 31) / 32), tb>>>(decW1, decW1T, HD, IND);

    // ---- encoder pass (shared for x and x_shf) ----
    auto encode = [&](const float* xin, float* zout) {
        mmagemm_k<<<dim3(GM, HD / 128), 256>>>(NN, HD, IND, xin, encW0T, nullptr, u512);
        {
            int n4 = NN * HD / 4;
            copy4_k<<<(n4 + 255) / 256, 256>>>((float4*)a512, (const float4*)u512, n4);
        }
        agg_k<<<AGG_BLOCKS, 256>>>(u512, a512, src, dst, HD);
        ln_relu_k<<<NN, 128>>>(a512, encb0, h512, HD);

        mmagemm_k<<<dim3(GM, ZD / 128), 256>>>(NN, ZD, HD, h512, encW1T, nullptr, u128);
        {
            int n4 = NN * ZD / 4;
            copy4_k<<<(n4 + 255) / 256, 256>>>((float4*)a128, (const float4*)u128, n4);
        }
        agg_k<<<AGG_BLOCKS, 256>>>(u128, a128, src, dst, ZD);
        ln_relu_k<<<NN, 128>>>(a128, encb1, zout, ZD);
    };

    encode(x, z);
    pool_k<<<(NN * 32 + 255) / 256, 256>>>(z, subix, o_zsub);

    encode(x_shf, zshf);
    pool_k<<<(NN * 32 + 255) / 256, 256>>>(zshf, subix, o_zshf);

    // ---- decoder ----
    zcat_k<<<(NN * 32 + 255) / 256, 256>>>(z, znb);
    bemb_k<<<(NN + 255) / 256, 256>>>(bl, beW0, beb0, beW1, beb1, znb);
    {
        int n4 = NN * DEC0D / 4;
        copy4_k<<<(n4 + 255) / 256, 256>>>((float4*)aznb, (const float4*)znb, n4);
    }
    agg_k<<<AGG_BLOCKS, 256>>>(znb, aznb, src, dst, DEC0D);
    mmagemm_k<<<dim3(GM, HD / 128), 256>>>(NN, HD, DEC0D, aznb, decW0T, nullptr, u512);
    ln_relu_k<<<NN, 128>>>(u512, decb0, h512, HD);
    {
        int n4 = NN * HD / 4;
        copy4_k<<<(n4 + 255) / 256, 256>>>((float4*)a512, (const float4*)h512, n4);
    }
    agg_k<<<AGG_BLOCKS, 256>>>(h512, a512, src, dst, HD);
    mmagemm_k<<<dim3(GM, IND / 128), 256>>>(NN, IND, HD, a512, decW1T, decb1, o_recon);

    // ---- heads ----
    bd_head_k<<<NN, 64>>>(o_zsub, bdW0, bdb0, bdW1, bdb1, o_lb);
    // M = z_sub_shf @ bil_W^T  -> BT = (bil_W^T)^T = bil_W itself
    mmagemm_k<<<dim3(GM, ZD / 128), 256>>>(NN, ZD, ZD, o_zshf, bilW, nullptr, u128);
    pair_k<<<(2 * PP * 32 + 255) / 256, 256>>>(o_zsub, u128, pos, neg, o_lp, o_ln);
}

// round 8
// speedup vs baseline: 3.0052x; 1.4572x over previous
#include <cuda_runtime.h>
#include <cuda_bf16.h>
#include <cstdint>

#define NN    30000
#define NN2   60000
#define EE    480000
#define E2    (2*EE)
#define KSUB  32
#define PP    16384
#define IND   1024
#define HD    512
#define ZD    128
#define BNC   8
#define DBC   16
#define DEC0D 144   // ZD + DBC

// ---------------- scratch (device globals; no allocation allowed) ----------
__device__ float g_u512[(size_t)NN2 * HD];   // enc L1 pre-agg (both), dec L1 reuse
__device__ float g_h512[(size_t)NN2 * HD];   // enc L1 act (both); dec: [0:NN)=h, [NN:2NN)=a512
__device__ float g_u128[(size_t)NN2 * ZD];   // enc L2 pre-agg; later bilinear M
__device__ float g_zz[(size_t)NN2 * ZD];     // z | z_shf
__device__ float g_znb[(size_t)NN * DEC0D];
__device__ float g_aznb[(size_t)NN * DEC0D];
// transposed weights (B^T, [N,K] K-major)
__device__ float g_encW0T[(size_t)HD * IND];
__device__ float g_encW1T[(size_t)ZD * HD];
__device__ float g_decW0T[(size_t)HD * DEC0D];
__device__ float g_decW1T[(size_t)IND * HD];
// CSR (virtual 60000-node graph = two copies of the 30000-node graph)
__device__ int g_cnt[NN2];
__device__ int g_fill[NN2];
__device__ int g_off[NN2 + 1];
__device__ int g_csr[E2];

// ======================= mma.sync tf32 helpers ===========================
__device__ __forceinline__ uint32_t su32(const void* p) {
    return (uint32_t)__cvta_generic_to_shared(p);
}
__device__ __forceinline__ uint32_t f2tf32(float x) {
    uint32_t u;
    asm("cvt.rna.tf32.f32 %0, %1;" : "=r"(u) : "f"(x));
    return u;
}
__device__ __forceinline__ void ldsm4(uint32_t* r, uint32_t addr) {
    asm volatile("ldmatrix.sync.aligned.m8n8.x4.shared.b16 {%0,%1,%2,%3}, [%4];"
                 : "=r"(r[0]), "=r"(r[1]), "=r"(r[2]), "=r"(r[3]) : "r"(addr));
}
__device__ __forceinline__ void mma_tf32(float* c, const uint32_t* a, const uint32_t* b) {
    asm volatile(
        "mma.sync.aligned.m16n8k8.row.col.f32.tf32.tf32.f32 "
        "{%0,%1,%2,%3}, {%4,%5,%6,%7}, {%8,%9}, {%0,%1,%2,%3};"
        : "+f"(c[0]), "+f"(c[1]), "+f"(c[2]), "+f"(c[3])
        : "r"(a[0]), "r"(a[1]), "r"(a[2]), "r"(a[3]), "r"(b[0]), "r"(b[1]));
}

// ---------------- tensor-core tf32 GEMM (mma.sync, 2-stage) ---------------
// C[..] = A[M,Kd] @ BT[Nc,Kd]^T.  Two A "sides" supported:
//   side = blockIdx.x / sblocks  (A0 rows -> C rows [0,Meach), A1 -> [Meach,2*Meach))
// Block 128x128xK16, 8 warps (2x4), warp tile 64x32. Kd%16==0, Nc%128==0.
#define RS 20
__global__ __launch_bounds__(256) void mmagemm_k(
    int Meach, int Nc, int Kd, int sblocks,
    const float* __restrict__ A0, const float* __restrict__ A1,
    const float* __restrict__ BT,
    const float* __restrict__ bias, float* __restrict__ C)
{
    __shared__ __align__(16) float As[2][128 * RS];
    __shared__ __align__(16) float Bs[2][128 * RS];

    const int tid  = threadIdx.x;
    const int lane = tid & 31;
    const int wid  = tid >> 5;
    const int wm   = wid >> 2;
    const int wn   = wid & 3;
    const int side = blockIdx.x / sblocks;
    const int brow = (blockIdx.x - side * sblocks) * 128;
    const int bcol = blockIdx.y * 128;
    const float* __restrict__ A = side ? A1 : A0;
    const size_t crow0 = (size_t)side * Meach;

    float c[4][4][4];
#pragma unroll
    for (int i = 0; i < 4; i++)
#pragma unroll
        for (int j = 0; j < 4; j++)
#pragma unroll
            for (int k = 0; k < 4; k++) c[i][j][k] = 0.f;

    const int lr = tid >> 2;
    const int lc = (tid & 3) * 4;

    float4 ra[2], rb[2];
    auto ldg = [&](int k0) {
#pragma unroll
        for (int p = 0; p < 2; p++) {
            const int r = p * 64 + lr;
            const int gr = brow + r;
            float4 v = make_float4(0.f, 0.f, 0.f, 0.f);
            if (gr < Meach) v = *(const float4*)(A + (size_t)gr * Kd + k0 + lc);
            ra[p] = v;
            rb[p] = *(const float4*)(BT + (size_t)(bcol + r) * Kd + k0 + lc);
        }
    };
    auto sts = [&](int buf) {
#pragma unroll
        for (int p = 0; p < 2; p++) {
            const int r = p * 64 + lr;
            uint4 va, vb;
            va.x = f2tf32(ra[p].x); va.y = f2tf32(ra[p].y);
            va.z = f2tf32(ra[p].z); va.w = f2tf32(ra[p].w);
            vb.x = f2tf32(rb[p].x); vb.y = f2tf32(rb[p].y);
            vb.z = f2tf32(rb[p].z); vb.w = f2tf32(rb[p].w);
            *(uint4*)(As[buf] + r * RS + lc) = va;
            *(uint4*)(Bs[buf] + r * RS + lc) = vb;
        }
    };

    const int nch = Kd >> 4;
    const int l8 = lane & 7;
    const int lm = lane >> 3;

    ldg(0);
    sts(0);
    __syncthreads();

    for (int ci = 0; ci < nch; ci++) {
        const int cur = ci & 1;
        if (ci + 1 < nch) ldg((ci + 1) * 16);
        const uint32_t as_b = su32(As[cur]);
        const uint32_t bs_b = su32(Bs[cur]);
#pragma unroll
        for (int ks = 0; ks < 2; ks++) {
            uint32_t af[4][4], bf[2][4];
#pragma unroll
            for (int mt = 0; mt < 4; mt++) {
                const int r = wm * 64 + mt * 16 + l8 + (lm & 1) * 8;
                const int k = ks * 8 + (lm >> 1) * 4;
                ldsm4(af[mt], as_b + (uint32_t)(r * RS + k) * 4u);
            }
#pragma unroll
            for (int np = 0; np < 2; np++) {
                const int n = wn * 32 + np * 16 + l8 + (lm >> 1) * 8;
                const int k = ks * 8 + (lm & 1) * 4;
                ldsm4(bf[np], bs_b + (uint32_t)(n * RS + k) * 4u);
            }
#pragma unroll
            for (int mt = 0; mt < 4; mt++) {
#pragma unroll
                for (int np = 0; np < 2; np++) {
                    mma_tf32(c[mt][np * 2 + 0], af[mt], &bf[np][0]);
                    mma_tf32(c[mt][np * 2 + 1], af[mt], &bf[np][2]);
                }
            }
        }
        if (ci + 1 < nch) sts(1 - cur);
        __syncthreads();
    }

    const int row0 = brow + wm * 64 + (lane >> 2);
    const int col0 = bcol + wn * 32 + (lane & 3) * 2;
#pragma unroll
    for (int mt = 0; mt < 4; mt++) {
#pragma unroll
        for (int nt = 0; nt < 4; nt++) {
            const int cc = col0 + nt * 8;
            float bx = 0.f, by = 0.f;
            if (bias) { bx = bias[cc]; by = bias[cc + 1]; }
            const int r0 = row0 + mt * 16;
            if (r0 < Meach) {
                float2 v = make_float2(c[mt][nt][0] + bx, c[mt][nt][1] + by);
                *(float2*)(C + (crow0 + r0) * Nc + cc) = v;
            }
            if (r0 + 8 < Meach) {
                float2 v = make_float2(c[mt][nt][2] + bx, c[mt][nt][3] + by);
                *(float2*)(C + (crow0 + r0 + 8) * Nc + cc) = v;
            }
        }
    }
}

// ---------------- CSR build ----------------------------------------------
__global__ void zero_k(int* a, int n)
{
    int i = blockIdx.x * blockDim.x + threadIdx.x;
    if (i < n) a[i] = 0;
}
__global__ void hist_k(const int* __restrict__ dst)
{
    int e = blockIdx.x * blockDim.x + threadIdx.x;
    if (e >= E2) return;
    int d = (e < EE) ? dst[e] : dst[e - EE] + NN;
    atomicAdd(&g_cnt[d], 1);
}
__global__ void scan_k()
{
    const int t = threadIdx.x;           // 256 threads, 1 block
    const int chunk = (NN2 + 255) / 256; // 235
    int beg = t * chunk;
    int end = beg + chunk; if (end > NN2) end = NN2;
    if (beg > NN2) beg = NN2;
    int s = 0;
    for (int i = beg; i < end; i++) s += g_cnt[i];
    __shared__ int part[257];
    part[t] = s;
    __syncthreads();
    if (t == 0) {
        int r = 0;
        for (int i = 0; i < 256; i++) { int v = part[i]; part[i] = r; r += v; }
        part[256] = r;
        g_off[NN2] = r;
    }
    __syncthreads();
    int run = part[t];
    for (int i = beg; i < end; i++) { g_off[i] = run; run += g_cnt[i]; }
}
__global__ void scatter_k(const int* __restrict__ src, const int* __restrict__ dst)
{
    int e = blockIdx.x * blockDim.x + threadIdx.x;
    if (e >= E2) return;
    int s, d;
    if (e < EE) { s = src[e];      d = dst[e]; }
    else        { s = src[e - EE] + NN; d = dst[e - EE] + NN; }
    int p = g_off[d] + atomicAdd(&g_fill[d], 1);
    g_csr[p] = s;
}

// ---------------- fused self+agg (+bias+LN+ReLU), warp per node -----------
template<int D4PL, bool DOLN>
__global__ __launch_bounds__(256) void agg_csr_k(
    const float4* __restrict__ u, float4* __restrict__ out,
    const float* __restrict__ bias, int D, int nNodes)
{
    int w = (blockIdx.x * blockDim.x + threadIdx.x) >> 5;
    if (w >= nNodes) return;
    const int lane = threadIdx.x & 31;
    const int D4 = D >> 2;

    float4 acc[D4PL];
#pragma unroll
    for (int i = 0; i < D4PL; i++) {
        int c = lane + 32 * i;
        acc[i] = (c < D4) ? u[(size_t)w * D4 + c] : make_float4(0.f, 0.f, 0.f, 0.f);
    }
    const int beg = g_off[w], end = g_off[w + 1];
    for (int e = beg; e < end; e++) {
        int s = g_csr[e];
        const float4* up = u + (size_t)s * D4;
#pragma unroll
        for (int i = 0; i < D4PL; i++) {
            int c = lane + 32 * i;
            if (c < D4) {
                float4 v = up[c];
                acc[i].x += v.x; acc[i].y += v.y; acc[i].z += v.z; acc[i].w += v.w;
            }
        }
    }
    if (DOLN) {
#pragma unroll
        for (int i = 0; i < D4PL; i++) {
            int c = lane + 32 * i;
            if (c < D4) {
                float4 b = ((const float4*)bias)[c];
                acc[i].x += b.x; acc[i].y += b.y; acc[i].z += b.z; acc[i].w += b.w;
            }
        }
        float s = 0.f, ss = 0.f;
#pragma unroll
        for (int i = 0; i < D4PL; i++) {
            int c = lane + 32 * i;
            if (c < D4) {
                s  += acc[i].x + acc[i].y + acc[i].z + acc[i].w;
                ss += acc[i].x * acc[i].x + acc[i].y * acc[i].y
                    + acc[i].z * acc[i].z + acc[i].w * acc[i].w;
            }
        }
#pragma unroll
        for (int o = 16; o > 0; o >>= 1) {
            s  += __shfl_xor_sync(0xffffffffu, s, o);
            ss += __shfl_xor_sync(0xffffffffu, ss, o);
        }
        float mean = s / D;
        float var  = ss / D - mean * mean;
        float inv  = rsqrtf(var + 1e-5f);
#pragma unroll
        for (int i = 0; i < D4PL; i++) {
            acc[i].x = fmaxf((acc[i].x - mean) * inv, 0.f);
            acc[i].y = fmaxf((acc[i].y - mean) * inv, 0.f);
            acc[i].z = fmaxf((acc[i].z - mean) * inv, 0.f);
            acc[i].w = fmaxf((acc[i].w - mean) * inv, 0.f);
        }
    }
#pragma unroll
    for (int i = 0; i < D4PL; i++) {
        int c = lane + 32 * i;
        if (c < D4) out[(size_t)w * D4 + c] = acc[i];
    }
}

// ---------------- weight transpose ---------------------------------------
__global__ void transpose_k(const float* __restrict__ in, float* __restrict__ out,
                            int R, int C)
{
    __shared__ float t[32][33];
    int bx = blockIdx.x * 32, by = blockIdx.y * 32;
    int x = bx + threadIdx.x;
#pragma unroll
    for (int j = 0; j < 32; j += 8) {
        int y = by + threadIdx.y + j;
        if (x < C && y < R) t[threadIdx.y + j][threadIdx.x] = in[(size_t)y * C + x];
    }
    __syncthreads();
    int ox = by + threadIdx.x;
#pragma unroll
    for (int j = 0; j < 32; j += 8) {
        int oy = bx + threadIdx.y + j;
        if (ox < R && oy < C) out[(size_t)oy * R + ox] = t[threadIdx.x][threadIdx.y + j];
    }
}

// ---------------- standalone LayerNorm(+bias)+ReLU (decoder L1) -----------
__global__ void ln_relu_k(const float* __restrict__ v, const float* __restrict__ b,
                          float* __restrict__ out, int D)
{
    int row = blockIdx.x;
    int t = threadIdx.x;
    const float* vr = v + (size_t)row * D;
    float* orow = out + (size_t)row * D;
    int per = D >> 7;
    float vals[4];
    float s = 0.f, ss = 0.f;
    for (int c = 0; c < per; c++) {
        float x = vr[c * 128 + t] + b[c * 128 + t];
        vals[c] = x;
        s += x; ss += x * x;
    }
#pragma unroll
    for (int o = 16; o > 0; o >>= 1) {
        s  += __shfl_xor_sync(0xffffffffu, s, o);
        ss += __shfl_xor_sync(0xffffffffu, ss, o);
    }
    __shared__ float sh[8];
    int wid = t >> 5;
    if ((t & 31) == 0) { sh[wid] = s; sh[4 + wid] = ss; }
    __syncthreads();
    float st  = sh[0] + sh[1] + sh[2] + sh[3];
    float sst = sh[4] + sh[5] + sh[6] + sh[7];
    float mean = st / D;
    float var  = sst / D - mean * mean;
    float inv  = rsqrtf(var + 1e-5f);
    for (int c = 0; c < per; c++)
        orow[c * 128 + t] = fmaxf((vals[c] - mean) * inv, 0.f);
}

// ---------------- subgraph mean pool over both halves ---------------------
__global__ void pool2_k(const float* __restrict__ zz, const int* __restrict__ idx,
                        float* __restrict__ o_zsub, float* __restrict__ o_zshf)
{
    int w = (blockIdx.x * blockDim.x + threadIdx.x) >> 5;
    if (w >= NN2) return;
    int lane = threadIdx.x & 31;
    int side = (w >= NN) ? 1 : 0;
    int li = w - side * NN;
    int base = side * NN;
    int mi = __ldg(idx + (size_t)li * KSUB + lane);
    float4 acc = make_float4(0.f, 0.f, 0.f, 0.f);
#pragma unroll
    for (int k = 0; k < KSUB; k++) {
        int j = __shfl_sync(0xffffffffu, mi, k) + base;
        float4 v = ((const float4*)(zz + (size_t)j * ZD))[lane];
        acc.x += v.x; acc.y += v.y; acc.z += v.z; acc.w += v.w;
    }
    const float s = 1.f / KSUB;
    float* o = side ? o_zshf : o_zsub;
    ((float4*)(o + (size_t)li * ZD))[lane] =
        make_float4(acc.x * s, acc.y * s, acc.z * s, acc.w * s);
}

// ---------------- batch encoder MLP: writes znb[:,128:144] ---------------
__global__ void bemb_k(const float* __restrict__ bl,
                       const float* __restrict__ W0, const float* __restrict__ b0,
                       const float* __restrict__ W1, const float* __restrict__ b1,
                       float* __restrict__ znb)
{
    int i = blockIdx.x * blockDim.x + threadIdx.x;
    if (i >= NN) return;
    float in[BNC];
#pragma unroll
    for (int k = 0; k < BNC; k++) in[k] = bl[(size_t)i * BNC + k];
    float h[12];
#pragma unroll
    for (int j = 0; j < 12; j++) {
        float a = b0[j];
#pragma unroll
        for (int k = 0; k < BNC; k++) a = fmaf(in[k], W0[k * 12 + j], a);
        h[j] = fmaxf(a, 0.f);
    }
#pragma unroll
    for (int j = 0; j < DBC; j++) {
        float a = b1[j];
#pragma unroll
        for (int k = 0; k < 12; k++) a = fmaf(h[k], W1[k * DBC + j], a);
        znb[(size_t)i * DEC0D + ZD + j] = a;
    }
}

// ---------------- copy z_node into znb[:,0:128] ---------------------------
__global__ void zcat_k(const float* __restrict__ z, float* __restrict__ znb)
{
    int i = blockIdx.x * blockDim.x + threadIdx.x;
    if (i >= NN * 32) return;
    int node = i >> 5, c = i & 31;
    ((float4*)(znb + (size_t)node * DEC0D))[c] =
        ((const float4*)(z + (size_t)node * ZD))[c];
}

// ---------------- batch discriminator head --------------------------------
__global__ void bd_head_k(const float* __restrict__ zsub,
                          const float* __restrict__ W0, const float* __restrict__ b0,
                          const float* __restrict__ W1, const float* __restrict__ b1,
                          float* __restrict__ out)
{
    int i = blockIdx.x;
    int j = threadIdx.x;  // 64
    __shared__ float zs[128];
    __shared__ float hs[64];
    zs[j]      = zsub[(size_t)i * ZD + j];
    zs[j + 64] = zsub[(size_t)i * ZD + 64 + j];
    __syncthreads();
    float a = b0[j];
#pragma unroll 8
    for (int k = 0; k < 128; k++) a = fmaf(zs[k], W0[k * 64 + j], a);
    hs[j] = fmaxf(a, 0.f);
    __syncthreads();
    if (j < BNC) {
        float o = b1[j];
#pragma unroll 8
        for (int k = 0; k < 64; k++) o = fmaf(hs[k], W1[k * BNC + j], o);
        out[(size_t)i * BNC + j] = o;
    }
}

// ---------------- bilinear pair dots (warp per pair) ----------------------
__global__ void pair_k(const float* __restrict__ zsub, const float* __restrict__ Mm,
                       const int* __restrict__ pos, const int* __restrict__ neg,
                       float* __restrict__ lp, float* __restrict__ lng)
{
    int w = (blockIdx.x * blockDim.x + threadIdx.x) >> 5;
    if (w >= 2 * PP) return;
    int lane = threadIdx.x & 31;
    bool isneg = (w >= PP);
    int p = isneg ? w - PP : w;
    int ia = __ldg(pos + p);
    int ib = isneg ? __ldg(neg + p) : ia;
    float4 a = ((const float4*)(zsub + (size_t)ia * ZD))[lane];
    float4 b = ((const float4*)(Mm + (size_t)ib * ZD))[lane];
    float s = a.x * b.x + a.y * b.y + a.z * b.z + a.w * b.w;
#pragma unroll
    for (int o = 16; o > 0; o >>= 1) s += __shfl_xor_sync(0xffffffffu, s, o);
    if (lane == 0) (isneg ? lng : lp)[p] = s;
}

// =========================================================================
extern "C" void kernel_launch(void* const* d_in, const int* in_sizes, int n_in,
                              void* d_out, int out_size)
{
    const float* x     = (const float*)d_in[0];
    const float* x_shf = (const float*)d_in[1];
    const float* bl    = (const float*)d_in[2];
    const float* encW0 = (const float*)d_in[3];
    const float* encb0 = (const float*)d_in[4];
    const float* encW1 = (const float*)d_in[5];
    const float* encb1 = (const float*)d_in[6];
    const float* decW0 = (const float*)d_in[7];
    const float* decb0 = (const float*)d_in[8];
    const float* decW1 = (const float*)d_in[9];
    const float* decb1 = (const float*)d_in[10];
    const float* beW0  = (const float*)d_in[11];
    const float* beb0  = (const float*)d_in[12];
    const float* beW1  = (const float*)d_in[13];
    const float* beb1  = (const float*)d_in[14];
    const float* bdW0  = (const float*)d_in[15];
    const float* bdb0  = (const float*)d_in[16];
    const float* bdW1  = (const float*)d_in[17];
    const float* bdb1  = (const float*)d_in[18];
    const float* bilW  = (const float*)d_in[19];
    const int*   eidx  = (const int*)d_in[20];
    const int*   subix = (const int*)d_in[21];
    const int*   pos   = (const int*)d_in[22];
    const int*   neg   = (const int*)d_in[23];
    const int* src = eidx;
    const int* dst = eidx + EE;

    float* out     = (float*)d_out;
    float* o_zsub  = out;
    float* o_zshf  = o_zsub  + (size_t)NN * ZD;
    float* o_recon = o_zshf  + (size_t)NN * ZD;
    float* o_lp    = o_recon + (size_t)NN * IND;
    float* o_ln    = o_lp + PP;
    float* o_lb    = o_ln + PP;

    float *u512, *h512, *u128, *zz, *znb, *aznb;
    float *encW0T, *encW1T, *decW0T, *decW1T;
    int *cnt, *fill;
    cudaGetSymbolAddress((void**)&u512,  g_u512);
    cudaGetSymbolAddress((void**)&h512,  g_h512);
    cudaGetSymbolAddress((void**)&u128,  g_u128);
    cudaGetSymbolAddress((void**)&zz,    g_zz);
    cudaGetSymbolAddress((void**)&znb,   g_znb);
    cudaGetSymbolAddress((void**)&aznb,  g_aznb);
    cudaGetSymbolAddress((void**)&encW0T, g_encW0T);
    cudaGetSymbolAddress((void**)&encW1T, g_encW1T);
    cudaGetSymbolAddress((void**)&decW0T, g_decW0T);
    cudaGetSymbolAddress((void**)&decW1T, g_decW1T);
    cudaGetSymbolAddress((void**)&cnt,  g_cnt);
    cudaGetSymbolAddress((void**)&fill, g_fill);

    float* a512 = h512 + (size_t)NN * HD;   // reuse second half of h512 as dec a512
    float* zshf = zz + (size_t)NN * ZD;

    const int GM  = (NN + 127) / 128;    // 235
    const int WPB = 8;                   // warps per block in agg kernels
    dim3 tb(32, 8);

    // ---- CSR build (virtual 60000-node graph) ----
    zero_k<<<(NN2 + 255) / 256, 256>>>(cnt, NN2);
    zero_k<<<(NN2 + 255) / 256, 256>>>(fill, NN2);
    hist_k<<<(E2 + 255) / 256, 256>>>(dst);
    scan_k<<<1, 256>>>();
    scatter_k<<<(E2 + 255) / 256, 256>>>(src, dst);

    // ---- weight transposes ----
    transpose_k<<<dim3((HD + 31) / 32, (IND + 31) / 32), tb>>>(encW0, encW0T, IND, HD);
    transpose_k<<<dim3((ZD + 31) / 32, (HD + 31) / 32), tb>>>(encW1, encW1T, HD, ZD);
    transpose_k<<<dim3((HD + 31) / 32, (DEC0D + 31) / 32), tb>>>(decW0, decW0T, DEC0D, HD);
    transpose_k<<<dim3((IND + 31) / 32, (HD + 31) / 32), tb>>>(decW1, decW1T, HD, IND);

    // ---- encoder, both graphs at once ----
    // L1: u512[0:60000) = [x; x_shf] @ encW0
    mmagemm_k<<<dim3(2 * GM, HD / 128), 256>>>(NN, HD, IND, GM, x, x_shf,
                                               encW0T, nullptr, u512);
    agg_csr_k<4, true><<<(NN2 + WPB - 1) / WPB, 32 * WPB>>>(
        (const float4*)u512, (float4*)h512, encb0, HD, NN2);
    // L2: u128 = h512 @ encW1 (contiguous M=60000)
    mmagemm_k<<<dim3(2 * GM, ZD / 128), 256>>>(NN2, ZD, HD, 2 * GM, h512, nullptr,
                                               encW1T, nullptr, u128);
    agg_csr_k<1, true><<<(NN2 + WPB - 1) / WPB, 32 * WPB>>>(
        (const float4*)u128, (float4*)zz, encb1, ZD, NN2);
    pool2_k<<<(NN2 * 32 + 255) / 256, 256>>>(zz, subix, o_zsub, o_zshf);

    // ---- decoder (first half: z) ----
    zcat_k<<<(NN * 32 + 255) / 256, 256>>>(zz, znb);
    bemb_k<<<(NN + 255) / 256, 256>>>(bl, beW0, beb0, beW1, beb1, znb);
    agg_csr_k<2, false><<<(NN + WPB - 1) / WPB, 32 * WPB>>>(
        (const float4*)znb, (float4*)aznb, nullptr, DEC0D, NN);
    mmagemm_k<<<dim3(GM, HD / 128), 256>>>(NN, HD, DEC0D, GM, aznb, nullptr,
                                           decW0T, nullptr, u512);
    ln_relu_k<<<NN, 128>>>(u512, decb0, h512, HD);
    agg_csr_k<4, false><<<(NN + WPB - 1) / WPB, 32 * WPB>>>(
        (const float4*)h512, (float4*)a512, nullptr, HD, NN);
    mmagemm_k<<<dim3(GM, IND / 128), 256>>>(NN, IND, HD, GM, a512, nullptr,
                                            decW1T, decb1, o_recon);

    // ---- heads ----
    bd_head_k<<<NN, 64>>>(o_zsub, bdW0, bdb0, bdW1, bdb1, o_lb);
    // M = z_sub_shf @ bil_W^T  -> BT = bil_W itself
    mmagemm_k<<<dim3(GM, ZD / 128), 256>>>(NN, ZD, ZD, GM, o_zshf, nullptr,
                                           bilW, nullptr, u128);
    pair_k<<<(2 * PP * 32 + 255) / 256, 256>>>(o_zsub, u128, pos, neg, o_lp, o_ln);
}